// round 1
// baseline (speedup 1.0000x reference)
#include <cuda_runtime.h>
#include <math.h>

#define NN 100000
#define EE 1600000

// ---- scratch (device globals; no allocation allowed) ----
__device__ int   g_deg[NN];
__device__ int   g_row_start[NN];
__device__ int   g_cursor[NN];
__device__ int   g_csr_src[EE];
__device__ float g_agg1[NN * 64];
__device__ float g_h[NN * 128];
__device__ float g_agg2[NN * 128];

// ---------------- CSR build ----------------

__global__ void k_zero() {
    int i = blockIdx.x * blockDim.x + threadIdx.x;
    if (i < NN) { g_deg[i] = 0; g_cursor[i] = 0; }
}

__global__ void k_count(const int* __restrict__ dst) {
    int e = blockIdx.x * blockDim.x + threadIdx.x;
    if (e < EE) atomicAdd(&g_deg[dst[e]], 1);
}

// single-block exclusive scan of g_deg -> g_row_start (N=100000, 1024 threads, ~98 elems/thread)
__global__ void k_scan() {
    __shared__ int ssum[1024];
    int tid = threadIdx.x;
    const int per = (NN + 1023) / 1024;  // 98
    int begin = tid * per;
    int end = begin + per; if (end > NN) end = NN;
    int s = 0;
    for (int i = begin; i < end; i++) s += g_deg[i];
    ssum[tid] = s;
    __syncthreads();
    // inclusive Hillis-Steele scan over 1024 partials
    for (int off = 1; off < 1024; off <<= 1) {
        int v = 0;
        if (tid >= off) v = ssum[tid - off];
        __syncthreads();
        ssum[tid] += v;
        __syncthreads();
    }
    int run = ssum[tid] - s;  // exclusive prefix for this segment
    for (int i = begin; i < end; i++) { g_row_start[i] = run; run += g_deg[i]; }
}

__global__ void k_fill(const int* __restrict__ src, const int* __restrict__ dst) {
    int e = blockIdx.x * blockDim.x + threadIdx.x;
    if (e < EE) {
        int d = dst[e];
        int pos = atomicAdd(&g_cursor[d], 1);
        g_csr_src[g_row_start[d] + pos] = src[e];
    }
}

// ---------------- aggregation (warp per node, register accumulation) ----------------

// C = 64: each lane owns a float2 (lane*2 .. lane*2+1)
__global__ void k_agg64(const float* __restrict__ feat) {
    int w = (blockIdx.x * blockDim.x + threadIdx.x) >> 5;
    int lane = threadIdx.x & 31;
    if (w >= NN) return;
    int start = g_row_start[w];
    int d = g_deg[w];
    const int* cs = g_csr_src + start;
    float ax0 = 0.f, ay0 = 0.f, ax1 = 0.f, ay1 = 0.f;
    float ax2 = 0.f, ay2 = 0.f, ax3 = 0.f, ay3 = 0.f;
    int j = 0;
    for (; j + 4 <= d; j += 4) {
        int s0 = cs[j], s1 = cs[j + 1], s2 = cs[j + 2], s3 = cs[j + 3];
        float2 v0 = ((const float2*)(feat + (size_t)s0 * 64))[lane];
        float2 v1 = ((const float2*)(feat + (size_t)s1 * 64))[lane];
        float2 v2 = ((const float2*)(feat + (size_t)s2 * 64))[lane];
        float2 v3 = ((const float2*)(feat + (size_t)s3 * 64))[lane];
        ax0 += v0.x; ay0 += v0.y;
        ax1 += v1.x; ay1 += v1.y;
        ax2 += v2.x; ay2 += v2.y;
        ax3 += v3.x; ay3 += v3.y;
    }
    for (; j < d; j++) {
        int s0 = cs[j];
        float2 v0 = ((const float2*)(feat + (size_t)s0 * 64))[lane];
        ax0 += v0.x; ay0 += v0.y;
    }
    int dd = d > 0 ? d : 1;
    float inv = 1.0f / (float)dd;
    float2 r;
    r.x = (ax0 + ax1 + ax2 + ax3) * inv;
    r.y = (ay0 + ay1 + ay2 + ay3) * inv;
    ((float2*)(g_agg1 + (size_t)w * 64))[lane] = r;
}

// C = 128 (aggregates g_h into g_agg2): each lane owns a float4
__global__ void k_agg128() {
    int w = (blockIdx.x * blockDim.x + threadIdx.x) >> 5;
    int lane = threadIdx.x & 31;
    if (w >= NN) return;
    int start = g_row_start[w];
    int d = g_deg[w];
    const int* cs = g_csr_src + start;
    float a0x = 0.f, a0y = 0.f, a0z = 0.f, a0w = 0.f;
    float a1x = 0.f, a1y = 0.f, a1z = 0.f, a1w = 0.f;
    int j = 0;
    for (; j + 2 <= d; j += 2) {
        int s0 = cs[j], s1 = cs[j + 1];
        float4 v0 = ((const float4*)(g_h + (size_t)s0 * 128))[lane];
        float4 v1 = ((const float4*)(g_h + (size_t)s1 * 128))[lane];
        a0x += v0.x; a0y += v0.y; a0z += v0.z; a0w += v0.w;
        a1x += v1.x; a1y += v1.y; a1z += v1.z; a1w += v1.w;
    }
    if (j < d) {
        int s0 = cs[j];
        float4 v0 = ((const float4*)(g_h + (size_t)s0 * 128))[lane];
        a0x += v0.x; a0y += v0.y; a0z += v0.z; a0w += v0.w;
    }
    int dd = d > 0 ? d : 1;
    float inv = 1.0f / (float)dd;
    float4 r;
    r.x = (a0x + a1x) * inv;
    r.y = (a0y + a1y) * inv;
    r.z = (a0z + a1z) * inv;
    r.w = (a0w + a1w) * inv;
    ((float4*)(g_agg2 + (size_t)w * 128))[lane] = r;
}

// ---------------- fused linear layers ----------------

// h = relu(agg1 @ W1_l^T + b1 + x @ W1_r^T)     [N,64]x2 -> [N,128]
// 128 threads, 32 nodes/block. thread: 4 outputs (stride 32) x 8 nodes (stride 4).
__global__ void k_xform1(const float* __restrict__ x,
                         const float* __restrict__ W1l,
                         const float* __restrict__ W1r,
                         const float* __restrict__ b1) {
    extern __shared__ float sm[];
    float* Wl = sm;                 // [128][65]
    float* Wr = Wl + 128 * 65;      // [128][65]
    float* bs = Wr + 128 * 65;      // [128]
    float* As = bs + 128;           // [32][65]
    float* Xs = As + 32 * 65;       // [32][65]
    int tid = threadIdx.x;
    int n0 = blockIdx.x * 32;

    for (int idx = tid; idx < 128 * 64; idx += 128) {
        int o = idx >> 6, c = idx & 63;
        Wl[o * 65 + c] = W1l[idx];
        Wr[o * 65 + c] = W1r[idx];
    }
    bs[tid] = b1[tid];
    for (int idx = tid; idx < 32 * 64; idx += 128) {
        int n = idx >> 6, c = idx & 63;
        As[n * 65 + c] = g_agg1[(size_t)(n0 + n) * 64 + c];
        Xs[n * 65 + c] = x[(size_t)(n0 + n) * 64 + c];
    }
    __syncthreads();

    int ox = tid & 31;
    int ny = tid >> 5;
    float acc[8][4];
#pragma unroll
    for (int k = 0; k < 8; k++)
#pragma unroll
        for (int j = 0; j < 4; j++) acc[k][j] = 0.f;

#pragma unroll 4
    for (int c = 0; c < 64; c++) {
        float w0 = Wl[(ox) * 65 + c];
        float w1 = Wl[(ox + 32) * 65 + c];
        float w2 = Wl[(ox + 64) * 65 + c];
        float w3 = Wl[(ox + 96) * 65 + c];
#pragma unroll
        for (int k = 0; k < 8; k++) {
            float a = As[(ny + 4 * k) * 65 + c];
            acc[k][0] = fmaf(a, w0, acc[k][0]);
            acc[k][1] = fmaf(a, w1, acc[k][1]);
            acc[k][2] = fmaf(a, w2, acc[k][2]);
            acc[k][3] = fmaf(a, w3, acc[k][3]);
        }
    }
#pragma unroll 4
    for (int c = 0; c < 64; c++) {
        float w0 = Wr[(ox) * 65 + c];
        float w1 = Wr[(ox + 32) * 65 + c];
        float w2 = Wr[(ox + 64) * 65 + c];
        float w3 = Wr[(ox + 96) * 65 + c];
#pragma unroll
        for (int k = 0; k < 8; k++) {
            float a = Xs[(ny + 4 * k) * 65 + c];
            acc[k][0] = fmaf(a, w0, acc[k][0]);
            acc[k][1] = fmaf(a, w1, acc[k][1]);
            acc[k][2] = fmaf(a, w2, acc[k][2]);
            acc[k][3] = fmaf(a, w3, acc[k][3]);
        }
    }

#pragma unroll
    for (int k = 0; k < 8; k++) {
        int n = n0 + ny + 4 * k;
#pragma unroll
        for (int j = 0; j < 4; j++) {
            int o = ox + 32 * j;
            float v = acc[k][j] + bs[o];
            g_h[(size_t)n * 128 + o] = fmaxf(v, 0.f);
        }
    }
}

// out = sigmoid(agg2 @ W2_l^T + b2 + h @ W2_r^T)    [N,128]x2 -> [N,64]
__global__ void k_xform2(const float* __restrict__ W2l,
                         const float* __restrict__ W2r,
                         const float* __restrict__ b2,
                         float* __restrict__ out) {
    extern __shared__ float sm[];
    float* Wl = sm;                 // [64][129]
    float* Wr = Wl + 64 * 129;      // [64][129]
    float* bs = Wr + 64 * 129;      // [64]
    float* As = bs + 64;            // [32][129]
    float* Hs = As + 32 * 129;      // [32][129]
    int tid = threadIdx.x;
    int n0 = blockIdx.x * 32;

    for (int idx = tid; idx < 64 * 128; idx += 128) {
        int o = idx >> 7, c = idx & 127;
        Wl[o * 129 + c] = W2l[idx];
        Wr[o * 129 + c] = W2r[idx];
    }
    if (tid < 64) bs[tid] = b2[tid];
    for (int idx = tid; idx < 32 * 128; idx += 128) {
        int n = idx >> 7, c = idx & 127;
        As[n * 129 + c] = g_agg2[(size_t)(n0 + n) * 128 + c];
        Hs[n * 129 + c] = g_h[(size_t)(n0 + n) * 128 + c];
    }
    __syncthreads();

    int ox = tid & 31;
    int ny = tid >> 5;
    float acc[8][2];
#pragma unroll
    for (int k = 0; k < 8; k++) { acc[k][0] = 0.f; acc[k][1] = 0.f; }

#pragma unroll 4
    for (int c = 0; c < 128; c++) {
        float w0 = Wl[ox * 129 + c];
        float w1 = Wl[(ox + 32) * 129 + c];
#pragma unroll
        for (int k = 0; k < 8; k++) {
            float a = As[(ny + 4 * k) * 129 + c];
            acc[k][0] = fmaf(a, w0, acc[k][0]);
            acc[k][1] = fmaf(a, w1, acc[k][1]);
        }
    }
#pragma unroll 4
    for (int c = 0; c < 128; c++) {
        float w0 = Wr[ox * 129 + c];
        float w1 = Wr[(ox + 32) * 129 + c];
#pragma unroll
        for (int k = 0; k < 8; k++) {
            float a = Hs[(ny + 4 * k) * 129 + c];
            acc[k][0] = fmaf(a, w0, acc[k][0]);
            acc[k][1] = fmaf(a, w1, acc[k][1]);
        }
    }

#pragma unroll
    for (int k = 0; k < 8; k++) {
        int n = n0 + ny + 4 * k;
#pragma unroll
        for (int j = 0; j < 2; j++) {
            int o = ox + 32 * j;
            float v = acc[k][j] + bs[o];
            out[(size_t)n * 64 + o] = 1.0f / (1.0f + expf(-v));
        }
    }
}

// ---------------- launch ----------------

extern "C" void kernel_launch(void* const* d_in, const int* in_sizes, int n_in,
                              void* d_out, int out_size) {
    const float* x   = (const float*)d_in[0];
    const int*   ei  = (const int*)d_in[1];
    const float* W1l = (const float*)d_in[2];
    const float* W1r = (const float*)d_in[3];
    const float* b1  = (const float*)d_in[4];
    const float* W2l = (const float*)d_in[5];
    const float* W2r = (const float*)d_in[6];
    const float* b2  = (const float*)d_in[7];
    float* out = (float*)d_out;

    const int* src = ei;
    const int* dst = ei + EE;

    const int smem1 = (128 * 65 * 2 + 128 + 32 * 65 * 2) * (int)sizeof(float);   // ~83.7 KB
    const int smem2 = (64 * 129 * 2 + 64 + 32 * 129 * 2) * (int)sizeof(float);   // ~99.3 KB
    cudaFuncSetAttribute(k_xform1, cudaFuncAttributeMaxDynamicSharedMemorySize, smem1);
    cudaFuncSetAttribute(k_xform2, cudaFuncAttributeMaxDynamicSharedMemorySize, smem2);

    k_zero<<<(NN + 255) / 256, 256>>>();
    k_count<<<(EE + 255) / 256, 256>>>(dst);
    k_scan<<<1, 1024>>>();
    k_fill<<<(EE + 255) / 256, 256>>>(src, dst);

    k_agg64<<<NN / 8, 256>>>(x);                       // 12500 blocks, warp/node
    k_xform1<<<NN / 32, 128, smem1>>>(x, W1l, W1r, b1);

    k_agg128<<<NN / 8, 256>>>();
    k_xform2<<<NN / 32, 128, smem2>>>(W2l, W2r, b2, out);
}

// round 2
// speedup vs baseline: 1.4401x; 1.4401x over previous
#include <cuda_runtime.h>
#include <math.h>

#define NN 100000
#define EE 1600000
#define SW 129   // float stride for weight tiles
#define SA 129   // float2 stride for A/H tiles

// ---- scratch (device globals; no allocation allowed) ----
__device__ int   g_deg[NN];
__device__ int   g_row_start[NN];
__device__ int   g_cursor[NN];
__device__ int   g_csr_src[EE];
__device__ float g_agg1[NN * 64];
__device__ float g_p[NN * 64];
__device__ float g_r[NN * 64];

typedef unsigned long long u64;

__device__ __forceinline__ u64 ffma2(u64 a, u64 b, u64 c) {
    u64 d;
    asm("fma.rn.f32x2 %0, %1, %2, %3;" : "=l"(d) : "l"(a), "l"(b), "l"(c));
    return d;
}
__device__ __forceinline__ u64 pk2(float lo, float hi) {
    u64 r;
    asm("mov.b64 %0, {%1,%2};" : "=l"(r) : "f"(lo), "f"(hi));
    return r;
}
__device__ __forceinline__ void upk2(u64 v, float& lo, float& hi) {
    asm("mov.b64 {%0,%1}, %2;" : "=f"(lo), "=f"(hi) : "l"(v));
}

// ---------------- CSR build ----------------

__global__ void k_zero() {
    int i = blockIdx.x * blockDim.x + threadIdx.x;
    if (i < NN) { g_deg[i] = 0; g_cursor[i] = 0; }
}

__global__ void k_count(const int* __restrict__ dst) {
    int e = blockIdx.x * blockDim.x + threadIdx.x;
    if (e < EE) atomicAdd(&g_deg[dst[e]], 1);
}

__global__ void k_scan() {
    __shared__ int ssum[1024];
    int tid = threadIdx.x;
    const int per = (NN + 1023) / 1024;
    int begin = tid * per;
    int end = begin + per; if (end > NN) end = NN;
    int s = 0;
    for (int i = begin; i < end; i++) s += g_deg[i];
    ssum[tid] = s;
    __syncthreads();
    for (int off = 1; off < 1024; off <<= 1) {
        int v = 0;
        if (tid >= off) v = ssum[tid - off];
        __syncthreads();
        ssum[tid] += v;
        __syncthreads();
    }
    int run = ssum[tid] - s;
    for (int i = begin; i < end; i++) { g_row_start[i] = run; run += g_deg[i]; }
}

__global__ void k_fill(const int* __restrict__ src, const int* __restrict__ dst) {
    int e = blockIdx.x * blockDim.x + threadIdx.x;
    if (e < EE) {
        int d = dst[e];
        int pos = atomicAdd(&g_cursor[d], 1);
        g_csr_src[g_row_start[d] + pos] = src[e];
    }
}

// ---------------- layer-1 aggregation: mean of x over neighbors ----------------

__global__ void k_agg64(const float* __restrict__ feat) {
    int w = (blockIdx.x * blockDim.x + threadIdx.x) >> 5;
    int lane = threadIdx.x & 31;
    if (w >= NN) return;
    int start = g_row_start[w];
    int d = g_deg[w];
    const int* cs = g_csr_src + start;
    float ax0 = 0.f, ay0 = 0.f, ax1 = 0.f, ay1 = 0.f;
    float ax2 = 0.f, ay2 = 0.f, ax3 = 0.f, ay3 = 0.f;
    int j = 0;
    for (; j + 4 <= d; j += 4) {
        int s0 = cs[j], s1 = cs[j + 1], s2 = cs[j + 2], s3 = cs[j + 3];
        float2 v0 = ((const float2*)(feat + (size_t)s0 * 64))[lane];
        float2 v1 = ((const float2*)(feat + (size_t)s1 * 64))[lane];
        float2 v2 = ((const float2*)(feat + (size_t)s2 * 64))[lane];
        float2 v3 = ((const float2*)(feat + (size_t)s3 * 64))[lane];
        ax0 += v0.x; ay0 += v0.y;
        ax1 += v1.x; ay1 += v1.y;
        ax2 += v2.x; ay2 += v2.y;
        ax3 += v3.x; ay3 += v3.y;
    }
    for (; j < d; j++) {
        int s0 = cs[j];
        float2 v0 = ((const float2*)(feat + (size_t)s0 * 64))[lane];
        ax0 += v0.x; ay0 += v0.y;
    }
    int dd = d > 0 ? d : 1;
    float inv = 1.0f / (float)dd;
    float2 r;
    r.x = (ax0 + ax1 + ax2 + ax3) * inv;
    r.y = (ay0 + ay1 + ay2 + ay3) * inv;
    ((float2*)(g_agg1 + (size_t)w * 64))[lane] = r;
}

// ---------------- fused transform: both layer GEMMs, h never leaves the block ----
// GEMM1: h = relu([agg1|x] @ [W1l;W1r]^T + b1)           (K=128 -> 128 outs)
// GEMM2: [p|r] = h @ [W2l;W2r]^T                          (K=128 -> 128 outs)
// 128 threads: o_t = tid&15 (16), n_t = tid>>4 (8). 8 outs x 8 nodes per thread.
// 64 nodes per block. Accumulators packed as f32x2 (fma.rn.f32x2).

__global__ __launch_bounds__(128, 1)
void k_xform(const float* __restrict__ x,
             const float* __restrict__ W1l, const float* __restrict__ W1r,
             const float* __restrict__ b1,
             const float* __restrict__ W2l, const float* __restrict__ W2r) {
    extern __shared__ float sm[];
    float*  W1c = sm;                       // [128][SW]
    float*  W2c = W1c + 128 * SW;           // [128][SW]
    float2* AH  = (float2*)(W2c + 128 * SW);// [64][SA] float2, duplicated {v,v}
    float*  bs  = (float*)(AH + 64 * SA);   // [128]
    int tid = threadIdx.x;
    int n0 = blockIdx.x * 64;

    // stage weights: W1c[o][c<64]=W1l, [c>=64]=W1r ; W2c[o<64]=W2l, [o>=64]=W2r
    for (int idx = tid; idx < 128 * 64; idx += 128) {
        int o = idx >> 6, c = idx & 63;
        W1c[o * SW + c]      = W1l[idx];
        W1c[o * SW + 64 + c] = W1r[idx];
    }
    for (int idx = tid; idx < 64 * 128; idx += 128) {
        int o = idx >> 7, c = idx & 127;
        W2c[o * SW + c]        = W2l[idx];
        W2c[(o + 64) * SW + c] = W2r[idx];
    }
    bs[tid] = b1[tid];
    // stage A = [agg1 | x] duplicated
    for (int idx = tid; idx < 64 * 64; idx += 128) {
        int n = idx >> 6, c = idx & 63;
        int nn = n0 + n; if (nn >= NN) nn = NN - 1;
        float va = g_agg1[(size_t)nn * 64 + c];
        float vx = x[(size_t)nn * 64 + c];
        AH[n * SA + c]      = make_float2(va, va);
        AH[n * SA + 64 + c] = make_float2(vx, vx);
    }
    __syncthreads();

    int o_t = tid & 15;
    int n_t = tid >> 4;
    const float2* arow = AH + n_t * 8 * SA;

    u64 acc[4][8];
#pragma unroll
    for (int j = 0; j < 4; j++)
#pragma unroll
        for (int k = 0; k < 8; k++) acc[j][k] = 0ULL;

    // ---- GEMM1 ----
#pragma unroll 2
    for (int c = 0; c < 128; c++) {
        u64 aa[8];
#pragma unroll
        for (int k = 0; k < 8; k++)
            aa[k] = *(const u64*)(arow + k * SA + c);
#pragma unroll
        for (int j = 0; j < 4; j++) {
            float wlo = W1c[(o_t + 32 * j) * SW + c];
            float whi = W1c[(o_t + 32 * j + 16) * SW + c];
            u64 wp = pk2(wlo, whi);
#pragma unroll
            for (int k = 0; k < 8; k++)
                acc[j][k] = ffma2(wp, aa[k], acc[j][k]);
        }
    }

    __syncthreads();   // everyone done reading A before overwrite

    // epilogue 1: bias + relu, write h duplicated into AH
#pragma unroll
    for (int j = 0; j < 4; j++) {
        int olo = o_t + 32 * j, ohi = olo + 16;
        float blo = bs[olo], bhi = bs[ohi];
#pragma unroll
        for (int k = 0; k < 8; k++) {
            float lo, hi;
            upk2(acc[j][k], lo, hi);
            lo = fmaxf(lo + blo, 0.f);
            hi = fmaxf(hi + bhi, 0.f);
            int n = n_t * 8 + k;
            AH[n * SA + olo] = make_float2(lo, lo);
            AH[n * SA + ohi] = make_float2(hi, hi);
            acc[j][k] = 0ULL;
        }
    }
    __syncthreads();

    // ---- GEMM2 ----
#pragma unroll 2
    for (int c = 0; c < 128; c++) {
        u64 aa[8];
#pragma unroll
        for (int k = 0; k < 8; k++)
            aa[k] = *(const u64*)(arow + k * SA + c);
#pragma unroll
        for (int j = 0; j < 4; j++) {
            float wlo = W2c[(o_t + 32 * j) * SW + c];
            float whi = W2c[(o_t + 32 * j + 16) * SW + c];
            u64 wp = pk2(wlo, whi);
#pragma unroll
            for (int k = 0; k < 8; k++)
                acc[j][k] = ffma2(wp, aa[k], acc[j][k]);
        }
    }

    // epilogue 2: j<2 -> p (outs 0..63), j>=2 -> r (outs 64..127)
#pragma unroll
    for (int j = 0; j < 4; j++) {
        int olo = o_t + 32 * j, ohi = olo + 16;
        float* dlo = (olo < 64) ? (g_p + olo) : (g_r + olo - 64);
        float* dhi = (ohi < 64) ? (g_p + ohi) : (g_r + ohi - 64);
#pragma unroll
        for (int k = 0; k < 8; k++) {
            int n = n0 + n_t * 8 + k;
            if (n < NN) {
                float lo, hi;
                upk2(acc[j][k], lo, hi);
                dlo[(size_t)n * 64] = lo;
                dhi[(size_t)n * 64] = hi;
            }
        }
    }
}

// ---------------- layer-2 aggregation + epilogue ----------------
// out = sigmoid(mean_j(p_j) + b2 + r)

__global__ void k_agg_out(const float* __restrict__ b2, float* __restrict__ out) {
    int w = (blockIdx.x * blockDim.x + threadIdx.x) >> 5;
    int lane = threadIdx.x & 31;
    if (w >= NN) return;
    int start = g_row_start[w];
    int d = g_deg[w];
    const int* cs = g_csr_src + start;
    float ax0 = 0.f, ay0 = 0.f, ax1 = 0.f, ay1 = 0.f;
    float ax2 = 0.f, ay2 = 0.f, ax3 = 0.f, ay3 = 0.f;
    int j = 0;
    for (; j + 4 <= d; j += 4) {
        int s0 = cs[j], s1 = cs[j + 1], s2 = cs[j + 2], s3 = cs[j + 3];
        float2 v0 = ((const float2*)(g_p + (size_t)s0 * 64))[lane];
        float2 v1 = ((const float2*)(g_p + (size_t)s1 * 64))[lane];
        float2 v2 = ((const float2*)(g_p + (size_t)s2 * 64))[lane];
        float2 v3 = ((const float2*)(g_p + (size_t)s3 * 64))[lane];
        ax0 += v0.x; ay0 += v0.y;
        ax1 += v1.x; ay1 += v1.y;
        ax2 += v2.x; ay2 += v2.y;
        ax3 += v3.x; ay3 += v3.y;
    }
    for (; j < d; j++) {
        int s0 = cs[j];
        float2 v0 = ((const float2*)(g_p + (size_t)s0 * 64))[lane];
        ax0 += v0.x; ay0 += v0.y;
    }
    int dd = d > 0 ? d : 1;
    float inv = 1.0f / (float)dd;
    float2 rr = ((const float2*)(g_r + (size_t)w * 64))[lane];
    float2 bb = ((const float2*)b2)[lane];
    float vx = (ax0 + ax1 + ax2 + ax3) * inv + bb.x + rr.x;
    float vy = (ay0 + ay1 + ay2 + ay3) * inv + bb.y + rr.y;
    float2 o;
    o.x = 1.0f / (1.0f + expf(-vx));
    o.y = 1.0f / (1.0f + expf(-vy));
    ((float2*)(out + (size_t)w * 64))[lane] = o;
}

// ---------------- launch ----------------

extern "C" void kernel_launch(void* const* d_in, const int* in_sizes, int n_in,
                              void* d_out, int out_size) {
    const float* x   = (const float*)d_in[0];
    const int*   ei  = (const int*)d_in[1];
    const float* W1l = (const float*)d_in[2];
    const float* W1r = (const float*)d_in[3];
    const float* b1  = (const float*)d_in[4];
    const float* W2l = (const float*)d_in[5];
    const float* W2r = (const float*)d_in[6];
    const float* b2  = (const float*)d_in[7];
    float* out = (float*)d_out;

    const int* src = ei;
    const int* dst = ei + EE;

    const int smem = (128 * SW * 2 + 128) * (int)sizeof(float)
                   + 64 * SA * (int)sizeof(float2);          // ~194 KB
    static int attr_set = 0;  // host-side, idempotent attribute config
    cudaFuncSetAttribute(k_xform, cudaFuncAttributeMaxDynamicSharedMemorySize, smem);
    (void)attr_set;

    k_zero<<<(NN + 255) / 256, 256>>>();
    k_count<<<(EE + 255) / 256, 256>>>(dst);
    k_scan<<<1, 1024>>>();
    k_fill<<<(EE + 255) / 256, 256>>>(src, dst);

    k_agg64<<<(NN + 7) / 8, 256>>>(x);
    k_xform<<<(NN + 63) / 64, 128, smem>>>(x, W1l, W1r, b1, W2l, W2r);
    k_agg_out<<<(NN + 7) / 8, 256>>>(b2, out);
}

// round 3
// speedup vs baseline: 1.7170x; 1.1923x over previous
#include <cuda_runtime.h>
#include <math.h>

#define NN 100000
#define EE 1600000
#define SOW 129   // float2 row stride for Wt2 (o-dim)
#define SAN 130   // float row stride for As (n-dim)

// ---- scratch (device globals; no allocation allowed) ----
__device__ int   g_deg[NN];
__device__ int   g_row_start[NN];
__device__ int   g_pos[EE];
__device__ int   g_csr_src[EE];
__device__ float g_agg1[NN * 64];
__device__ float g_p[NN * 64];
__device__ float g_r[NN * 64];

typedef unsigned long long u64;

__device__ __forceinline__ u64 ffma2(u64 a, u64 b, u64 c) {
    u64 d;
    asm("fma.rn.f32x2 %0, %1, %2, %3;" : "=l"(d) : "l"(a), "l"(b), "l"(c));
    return d;
}
__device__ __forceinline__ void upk2(u64 v, float& lo, float& hi) {
    asm("mov.b64 {%0,%1}, %2;" : "=f"(lo), "=f"(hi) : "l"(v));
}

// ---------------- CSR build ----------------

__global__ void k_zero() {
    int i = blockIdx.x * blockDim.x + threadIdx.x;
    if (i < NN) g_deg[i] = 0;
}

__global__ void k_count(const int* __restrict__ dst) {
    int e = blockIdx.x * blockDim.x + threadIdx.x;
    if (e < EE) {
        int pos = atomicAdd(&g_deg[dst[e]], 1);
        g_pos[e] = pos;
    }
}

__global__ void k_scan() {
    __shared__ int ssum[1024];
    int tid = threadIdx.x;
    const int per = (NN + 1023) / 1024;
    int begin = tid * per;
    int end = begin + per; if (end > NN) end = NN;
    int s = 0;
    for (int i = begin; i < end; i++) s += g_deg[i];
    ssum[tid] = s;
    __syncthreads();
    for (int off = 1; off < 1024; off <<= 1) {
        int v = 0;
        if (tid >= off) v = ssum[tid - off];
        __syncthreads();
        ssum[tid] += v;
        __syncthreads();
    }
    int run = ssum[tid] - s;
    for (int i = begin; i < end; i++) { g_row_start[i] = run; run += g_deg[i]; }
}

__global__ void k_fill(const int* __restrict__ src, const int* __restrict__ dst) {
    int e = blockIdx.x * blockDim.x + threadIdx.x;
    if (e < EE) {
        int d = dst[e];
        g_csr_src[g_row_start[d] + g_pos[e]] = src[e];
    }
}

// ---------------- layer-1 aggregation: mean of x over neighbors ----------------

__global__ void k_agg64(const float* __restrict__ feat) {
    int w = (blockIdx.x * blockDim.x + threadIdx.x) >> 5;
    int lane = threadIdx.x & 31;
    if (w >= NN) return;
    int start = g_row_start[w];
    int d = g_deg[w];
    const int* cs = g_csr_src + start;
    float ax[8], ay[8];
#pragma unroll
    for (int k = 0; k < 8; k++) { ax[k] = 0.f; ay[k] = 0.f; }
    int j = 0;
    for (; j + 8 <= d; j += 8) {
        int s[8];
#pragma unroll
        for (int k = 0; k < 8; k++) s[k] = cs[j + k];
#pragma unroll
        for (int k = 0; k < 8; k++) {
            float2 v = ((const float2*)(feat + (size_t)s[k] * 64))[lane];
            ax[k] += v.x; ay[k] += v.y;
        }
    }
    for (; j < d; j++) {
        float2 v = ((const float2*)(feat + (size_t)cs[j] * 64))[lane];
        ax[0] += v.x; ay[0] += v.y;
    }
    float sx = (ax[0] + ax[1]) + (ax[2] + ax[3]) + (ax[4] + ax[5]) + (ax[6] + ax[7]);
    float sy = (ay[0] + ay[1]) + (ay[2] + ay[3]) + (ay[4] + ay[5]) + (ay[6] + ay[7]);
    float inv = 1.0f / (float)(d > 0 ? d : 1);
    float2 r; r.x = sx * inv; r.y = sy * inv;
    ((float2*)(g_agg1 + (size_t)w * 64))[lane] = r;
}

// ---------------- fused transform: both layer GEMMs ----------------
// GEMM1: h = relu([agg1|x] @ [W1l;W1r]^T + b1)   K=128 -> 128 outs
// GEMM2: [p|r] = h @ [W2l;W2r]^T                 K=128 -> 128 outs
// 256 threads, 128 nodes/block. o_t=tid&15 (8 outs stride 16), n_t=tid>>4 (8 nodes).
// Accumulator f32x2 packs a NODE pair; weights stored duplicated {w,w}.

__global__ __launch_bounds__(256, 1)
void k_xform(const float* __restrict__ x,
             const float* __restrict__ W1l, const float* __restrict__ W1r,
             const float* __restrict__ b1,
             const float* __restrict__ W2l, const float* __restrict__ W2r) {
    extern __shared__ float sm[];
    float2* Wt2 = (float2*)sm;                 // [128 c][SOW] float2 {w,w}  (132 KB)
    float*  As  = (float*)(Wt2 + 128 * SOW);   // [128 c][SAN] float        (66.6 KB)
    float*  bs  = As + 128 * SAN;              // [128]
    int tid = threadIdx.x;
    int n0 = blockIdx.x * 128;

    // stage W1 duplicated, c-major: Wt2[c][o] = {w,w}; c<64 -> W1l, c>=64 -> W1r
    for (int idx = tid; idx < 128 * 64; idx += 256) {
        int o = idx >> 6, c = idx & 63;
        float wl = W1l[idx];
        float wr = W1r[idx];
        Wt2[c * SOW + o]        = make_float2(wl, wl);
        Wt2[(c + 64) * SOW + o] = make_float2(wr, wr);
    }
    if (tid < 128) bs[tid] = b1[tid];
    // stage A transposed: As[c][n]; c<64 from agg1, c>=64 from x
    for (int idx = tid; idx < 128 * 64; idx += 256) {
        int n = idx >> 6, c = idx & 63;
        int nn = n0 + n; if (nn >= NN) nn = NN - 1;
        As[c * SAN + n]        = g_agg1[(size_t)nn * 64 + c];
        As[(c + 64) * SAN + n] = x[(size_t)nn * 64 + c];
    }
    __syncthreads();

    int o_t = tid & 15;
    int n_t = tid >> 4;
    int nb = n_t * 8;

    u64 acc[8][4];
#pragma unroll
    for (int u = 0; u < 8; u++)
#pragma unroll
        for (int p = 0; p < 4; p++) acc[u][p] = 0ULL;

    // ---- GEMM1 ----
#pragma unroll 2
    for (int c = 0; c < 128; c++) {
        u64 aa[4];
#pragma unroll
        for (int p = 0; p < 4; p++)
            aa[p] = *(const u64*)(As + c * SAN + nb + 2 * p);
#pragma unroll
        for (int u = 0; u < 8; u++) {
            u64 wp = *(const u64*)(Wt2 + c * SOW + o_t + 16 * u);
#pragma unroll
            for (int p = 0; p < 4; p++)
                acc[u][p] = ffma2(wp, aa[p], acc[u][p]);
        }
    }

    __syncthreads();   // GEMM1 reads done; safe to overwrite Wt2 and As

    // stage W2 duplicated: o<64 -> W2l (p), o>=64 -> W2r (r)
    for (int idx = tid; idx < 64 * 128; idx += 256) {
        int o = idx >> 7, c = idx & 127;
        float wl = W2l[idx];
        float wr = W2r[idx];
        Wt2[c * SOW + o]      = make_float2(wl, wl);
        Wt2[c * SOW + o + 64] = make_float2(wr, wr);
    }
    // epilogue 1: bias + relu -> h into As[o][n]
#pragma unroll
    for (int u = 0; u < 8; u++) {
        int o = o_t + 16 * u;
        float b = bs[o];
#pragma unroll
        for (int p = 0; p < 4; p++) {
            float lo, hi;
            upk2(acc[u][p], lo, hi);
            lo = fmaxf(lo + b, 0.f);
            hi = fmaxf(hi + b, 0.f);
            *(float2*)(As + o * SAN + nb + 2 * p) = make_float2(lo, hi);
            acc[u][p] = 0ULL;
        }
    }
    __syncthreads();

    // ---- GEMM2 ----
#pragma unroll 2
    for (int c = 0; c < 128; c++) {
        u64 aa[4];
#pragma unroll
        for (int p = 0; p < 4; p++)
            aa[p] = *(const u64*)(As + c * SAN + nb + 2 * p);
#pragma unroll
        for (int u = 0; u < 8; u++) {
            u64 wp = *(const u64*)(Wt2 + c * SOW + o_t + 16 * u);
#pragma unroll
            for (int p = 0; p < 4; p++)
                acc[u][p] = ffma2(wp, aa[p], acc[u][p]);
        }
    }

    // epilogue 2: o<64 -> g_p, o>=64 -> g_r
#pragma unroll
    for (int u = 0; u < 8; u++) {
        int o = o_t + 16 * u;
        float* base = (o < 64) ? (g_p + o) : (g_r + (o - 64));
#pragma unroll
        for (int p = 0; p < 4; p++) {
            int n = n0 + nb + 2 * p;
            float lo, hi;
            upk2(acc[u][p], lo, hi);
            if (n < NN)     base[(size_t)n * 64]       = lo;
            if (n + 1 < NN) base[(size_t)(n + 1) * 64] = hi;
        }
    }
}

// ---------------- layer-2 aggregation + epilogue ----------------
// out = sigmoid(mean_j(p_j) + b2 + r)

__global__ void k_agg_out(const float* __restrict__ b2, float* __restrict__ out) {
    int w = (blockIdx.x * blockDim.x + threadIdx.x) >> 5;
    int lane = threadIdx.x & 31;
    if (w >= NN) return;
    int start = g_row_start[w];
    int d = g_deg[w];
    const int* cs = g_csr_src + start;
    float ax[8], ay[8];
#pragma unroll
    for (int k = 0; k < 8; k++) { ax[k] = 0.f; ay[k] = 0.f; }
    int j = 0;
    for (; j + 8 <= d; j += 8) {
        int s[8];
#pragma unroll
        for (int k = 0; k < 8; k++) s[k] = cs[j + k];
#pragma unroll
        for (int k = 0; k < 8; k++) {
            float2 v = ((const float2*)(g_p + (size_t)s[k] * 64))[lane];
            ax[k] += v.x; ay[k] += v.y;
        }
    }
    for (; j < d; j++) {
        float2 v = ((const float2*)(g_p + (size_t)cs[j] * 64))[lane];
        ax[0] += v.x; ay[0] += v.y;
    }
    float sx = (ax[0] + ax[1]) + (ax[2] + ax[3]) + (ax[4] + ax[5]) + (ax[6] + ax[7]);
    float sy = (ay[0] + ay[1]) + (ay[2] + ay[3]) + (ay[4] + ay[5]) + (ay[6] + ay[7]);
    float inv = 1.0f / (float)(d > 0 ? d : 1);
    float2 rr = ((const float2*)(g_r + (size_t)w * 64))[lane];
    float2 bb = ((const float2*)b2)[lane];
    float vx = sx * inv + bb.x + rr.x;
    float vy = sy * inv + bb.y + rr.y;
    float2 o;
    o.x = 1.0f / (1.0f + __expf(-vx));
    o.y = 1.0f / (1.0f + __expf(-vy));
    ((float2*)(out + (size_t)w * 64))[lane] = o;
}

// ---------------- launch ----------------

extern "C" void kernel_launch(void* const* d_in, const int* in_sizes, int n_in,
                              void* d_out, int out_size) {
    const float* x   = (const float*)d_in[0];
    const int*   ei  = (const int*)d_in[1];
    const float* W1l = (const float*)d_in[2];
    const float* W1r = (const float*)d_in[3];
    const float* b1  = (const float*)d_in[4];
    const float* W2l = (const float*)d_in[5];
    const float* W2r = (const float*)d_in[6];
    const float* b2  = (const float*)d_in[7];
    float* out = (float*)d_out;

    const int* src = ei;
    const int* dst = ei + EE;

    const int smem = 128 * SOW * (int)sizeof(float2)
                   + 128 * SAN * (int)sizeof(float)
                   + 128 * (int)sizeof(float);               // ~199 KB
    cudaFuncSetAttribute(k_xform, cudaFuncAttributeMaxDynamicSharedMemorySize, smem);

    k_zero<<<(NN + 255) / 256, 256>>>();
    k_count<<<(EE + 255) / 256, 256>>>(dst);
    k_scan<<<1, 1024>>>();
    k_fill<<<(EE + 255) / 256, 256>>>(src, dst);

    k_agg64<<<(NN + 7) / 8, 256>>>(x);
    k_xform<<<(NN + 127) / 128, 256, smem>>>(x, W1l, W1r, b1, W2l, W2r);
    k_agg_out<<<(NN + 7) / 8, 256>>>(b2, out);
}